// round 14
// baseline (speedup 1.0000x reference)
#include <cuda_runtime.h>
#include <cuda_fp16.h>
#include <cstdint>

#define TTOK 8192
#define DDIM 1024
#define HDIM 4096
#define NEXP 8
#define MAXTILE 144

// prep_kernel block-range dispatch
#define PREP_RT 32
#define PREP_RX 512
#define PREP_W1 8192
#define PREP_W2 8192
#define PREP_TOTAL (PREP_RT + PREP_RX + PREP_W1 + PREP_W2)

// a-feature availability for the CURRENT compilation target
#if defined(__CUDA_ARCH_FEAT_SM103_ALL) || defined(__CUDA_ARCH_FEAT_SM100_ALL)
#define HAS_TC 1
#else
#define HAS_TC 0
#endif

// ---------------- scratch (device globals; no runtime allocation) -----------
__device__ int    g_use_tc;
__device__ int    g_count[NEXP];
__device__ int    g_tok [NEXP][TTOK];
__device__ int    g_aid [NEXP][TTOK];
__device__ float  g_gate[NEXP][TTOK];
__device__ int    g_tile_e [160];                         // flat M-tile list (128-row tiles)
__device__ int    g_tile_m0[160];
__device__ int    g_ntile;
__device__ __half g_xh  [(size_t)TTOK * DDIM];            //  16 MB fp16 x
__device__ __half g_w1t [(size_t)NEXP * HDIM * DDIM];     //  64 MB W1^T fp16 (K-major)
__device__ __half g_w2t [(size_t)NEXP * DDIM * HDIM];     //  64 MB W2^T fp16 (K-major)
__device__ __half g_hscr[(size_t)2 * TTOK * HDIM];        // 134 MB h by aid (fp16)
__device__ __half g_oscr[(size_t)2 * TTOK * DDIM];        //  34 MB per-slot out (fp16)

// ---------------- small helpers ---------------------------------------------
__device__ __forceinline__ uint32_t smem_u32(const void* p) {
    uint32_t a;
    asm("{ .reg .u64 t; cvta.to.shared.u64 t, %1; cvt.u32.u64 %0, t; }" : "=r"(a) : "l"(p));
    return a;
}
__device__ __forceinline__ void cp16(void* dst, const void* src) {
    unsigned s = (unsigned)__cvta_generic_to_shared(dst);
    asm volatile("cp.async.cg.shared.global [%0], [%1], 16;" :: "r"(s), "l"(src));
}
__device__ __forceinline__ void cp_commit() { asm volatile("cp.async.commit_group;"); }
__device__ __forceinline__ void cp_wait1()  { asm volatile("cp.async.wait_group 1;"); }
__device__ __forceinline__ void cp_wait0()  { asm volatile("cp.async.wait_group 0;"); }

// fp16 mma.sync m16n8k16, fp32 accumulate (fallback path)
__device__ __forceinline__ void mma16(float* c, const unsigned* a, const unsigned* b) {
    asm volatile(
        "mma.sync.aligned.m16n8k16.row.col.f32.f16.f16.f32 "
        "{%0,%1,%2,%3}, {%4,%5,%6,%7}, {%8,%9}, {%0,%1,%2,%3};"
        : "+f"(c[0]), "+f"(c[1]), "+f"(c[2]), "+f"(c[3])
        : "r"(a[0]), "r"(a[1]), "r"(a[2]), "r"(a[3]), "r"(b[0]), "r"(b[1]));
}

// ---------------- init (probe + zero counts) ---------------------------------
__global__ void init_kernel() {
    if (threadIdx.x == 0) g_use_tc = HAS_TC;
    if (threadIdx.x < NEXP) g_count[threadIdx.x] = 0;
}

// ---------------- fused prep: router + round_x + both W transposes ----------
__global__ void __launch_bounds__(256)
prep_kernel(const float4* __restrict__ x,
            const float*  __restrict__ logits,
            const float*  __restrict__ noise,
            const float*  __restrict__ W1,
            const float*  __restrict__ W2,
            __half* __restrict__ w1t,
            __half* __restrict__ w2t) {
    __shared__ float ts[64][65];
    const int bid = blockIdx.x;

    if (bid < PREP_RT) {
        // ---- router: noisy top-2 + gates + expert lists (vectorized loads) --
        int t = bid * 256 + threadIdx.x;
        if (t >= TTOK) return;
        float4 L0 = *(const float4*)(logits + (size_t)t * NEXP);
        float4 L1 = *(const float4*)(logits + (size_t)t * NEXP + 4);
        float4 N0 = *(const float4*)(noise  + (size_t)t * NEXP);
        float4 N1 = *(const float4*)(noise  + (size_t)t * NEXP + 4);
        float l [8] = {L0.x, L0.y, L0.z, L0.w, L1.x, L1.y, L1.z, L1.w};
        float nz[8] = {N0.x, N0.y, N0.z, N0.w, N1.x, N1.y, N1.z, N1.w};

        float v0 = -1e30f, v1 = -1e30f;
        int i0 = 0, i1 = 0;
#pragma unroll
        for (int e = 0; e < NEXP; e++) {
            float sp = fmaxf(l[e], 0.f) + log1pf(expf(-fabsf(l[e])));
            float v  = l[e] + nz[e] * sp;
            if (v > v0)      { v1 = v0; i1 = i0; v0 = v; i0 = e; }
            else if (v > v1) { v1 = v;  i1 = e; }
        }
        float e1  = expf(v1 - v0);
        float den = 1.f + e1;
        float ga  = 1.f / den;
        float gb  = e1 / den;

        int s0 = atomicAdd(&g_count[i0], 1);
        g_tok[i0][s0] = t; g_aid[i0][s0] = 2 * t;     g_gate[i0][s0] = ga;
        int s1 = atomicAdd(&g_count[i1], 1);
        g_tok[i1][s1] = t; g_aid[i1][s1] = 2 * t + 1; g_gate[i1][s1] = gb;

    } else if (bid < PREP_RT + PREP_RX) {
        // ---- round_x: fp32 x -> fp16 (RNE), grid-stride --------------------
        int b = bid - PREP_RT;
        int i = b * 256 + threadIdx.x;
        const int stride = PREP_RX * 256;
        const int n4 = TTOK * DDIM / 4;
        for (; i < n4; i += stride) {
            float4 v = x[i];
            __half2 h0 = __floats2half2_rn(v.x, v.y);
            __half2 h1 = __floats2half2_rn(v.z, v.w);
            *(uint2*)(g_xh + (size_t)i * 4) =
                make_uint2(*(uint32_t*)&h0, *(uint32_t*)&h1);
        }

    } else {
        // ---- weight transpose + round: in[e][R][C] -> out[e][C][R] fp16 ----
        const float* in; __half* out; int R, C, bx, by, bz;
        if (bid < PREP_RT + PREP_RX + PREP_W1) {
            int b = bid - (PREP_RT + PREP_RX);
            in = W1; out = w1t; R = DDIM; C = HDIM;
            bx = b % (HDIM / 64);
            int r = b / (HDIM / 64);
            by = r % (DDIM / 64);
            bz = r / (DDIM / 64);
        } else {
            int b = bid - (PREP_RT + PREP_RX + PREP_W1);
            in = W2; out = w2t; R = HDIM; C = DDIM;
            bx = b % (DDIM / 64);
            int r = b / (DDIM / 64);
            by = r % (HDIM / 64);
            bz = r / (HDIM / 64);
        }
        size_t base = (size_t)bz * R * C;
        int c0 = bx * 64, r0 = by * 64;
        int tx = threadIdx.x & 15;          // float4 column
        int ty = threadIdx.x >> 4;          // row group
#pragma unroll
        for (int j = 0; j < 4; j++) {
            int row = ty + j * 16;
            float4 v = *(const float4*)(in + base + (size_t)(r0 + row) * C + c0 + tx * 4);
            ts[row][tx * 4 + 0] = v.x;
            ts[row][tx * 4 + 1] = v.y;
            ts[row][tx * 4 + 2] = v.z;
            ts[row][tx * 4 + 3] = v.w;
        }
        __syncthreads();
#pragma unroll
        for (int j = 0; j < 4; j++) {
            int oc = ty + j * 16;           // output row = original column
            __half2 h0 = __floats2half2_rn(ts[tx * 4 + 0][oc], ts[tx * 4 + 1][oc]);
            __half2 h1 = __floats2half2_rn(ts[tx * 4 + 2][oc], ts[tx * 4 + 3][oc]);
            *(uint2*)(out + base + (size_t)(c0 + oc) * R + r0 + tx * 4) =
                make_uint2(*(uint32_t*)&h0, *(uint32_t*)&h1);
        }
    }
}

// ---------------- flat M-tile list (128-row tiles) ---------------------------
__global__ void tilelist_kernel() {
    if (threadIdx.x != 0) return;
    int n = 0;
    for (int e = 0; e < NEXP; e++) {
        int cnt = g_count[e];
        for (int m0 = 0; m0 < cnt; m0 += 128) {
            g_tile_e [n] = e;
            g_tile_m0[n] = m0;
            n++;
        }
    }
    g_ntile = n;                       // <= 136 since sum(cnt) = 2*TTOK
}

// ============================================================================
// tcgen05 path — cg1 128M x 256N tiles, 2 CTAs/SM, 2-stage cp.async pipeline
// ============================================================================
#if HAS_TC

#define MBARRIER_INIT(addr, cnt) \
    asm volatile("mbarrier.init.shared.b64 [%0], %1;" :: "r"((uint32_t)(addr)), "r"((uint32_t)(cnt)) : "memory")

#define MBARRIER_WAIT_PARITY(mbar, par) do {                                            \
    uint32_t _m = (uint32_t)(mbar), _p = (uint32_t)(par), _d;                           \
    asm volatile("{\n\t.reg .pred p;\n\t"                                               \
        "mbarrier.try_wait.parity.acquire.cta.shared::cta.b64 p, [%1], %2;\n\t"         \
        "selp.b32 %0, 1, 0, p;\n\t}" : "=r"(_d) : "r"(_m), "r"(_p) : "memory");         \
    if (!_d) {                                                                          \
        asm volatile("{\n\t.reg .pred P1;\n\tWL_%=:\n\t"                                \
            "mbarrier.try_wait.parity.acquire.cta.shared::cta.b64 P1, [%0], %1, 0x989680;\n\t" \
            "@P1 bra.uni WD_%=;\n\tbra.uni WL_%=;\n\tWD_%=:\n\t}"                       \
            :: "r"(_m), "r"(_p) : "memory");                                            \
    }                                                                                   \
} while (0)

#define CPASYNC_ARRIVE_NOINC(mbar) \
    asm volatile("cp.async.mbarrier.arrive.noinc.shared::cta.b64 [%0];" :: "r"((uint32_t)(mbar)) : "memory")

#define TCGEN05_ALLOC(sa, n) \
    asm volatile("tcgen05.alloc.cta_group::1.sync.aligned.shared::cta.b32 [%0], %1;" \
                 :: "r"((uint32_t)(sa)), "r"((uint32_t)(n)) : "memory")
#define TCGEN05_DEALLOC(t, n) \
    asm volatile("tcgen05.dealloc.cta_group::1.sync.aligned.b32 %0, %1;" :: "r"(t), "r"((uint32_t)(n)))
#define TCGEN05_RELINQ() \
    asm volatile("tcgen05.relinquish_alloc_permit.cta_group::1.sync.aligned;")
#define TCGEN05_COMMIT(mbar) \
    asm volatile("tcgen05.commit.cta_group::1.mbarrier::arrive::one.shared::cluster.b64 [%0];" \
                 :: "r"((uint32_t)(mbar)) : "memory")
#define TCGEN05_FENCE_AFTER()  asm volatile("tcgen05.fence::after_thread_sync;" ::: "memory")
#define TCGEN05_FENCE_BEFORE() asm volatile("tcgen05.fence::before_thread_sync;" ::: "memory")
#define TCGEN05_WAIT_LD()      asm volatile("tcgen05.wait::ld.sync.aligned;" ::: "memory")
#define FENCE_PROXY_ASYNC()    asm volatile("fence.proxy.async.shared::cta;" ::: "memory")

#define TCGEN05_LD_32X32B_X32(r, ta) \
    asm volatile( \
        "tcgen05.ld.sync.aligned.32x32b.x32.b32 " \
        "{%0, %1, %2, %3, %4, %5, %6, %7, " \
        " %8, %9, %10, %11, %12, %13, %14, %15, " \
        " %16, %17, %18, %19, %20, %21, %22, %23, " \
        " %24, %25, %26, %27, %28, %29, %30, %31}, [%32];" \
        : "=r"((r)[0]),  "=r"((r)[1]),  "=r"((r)[2]),  "=r"((r)[3]), \
          "=r"((r)[4]),  "=r"((r)[5]),  "=r"((r)[6]),  "=r"((r)[7]), \
          "=r"((r)[8]),  "=r"((r)[9]),  "=r"((r)[10]), "=r"((r)[11]), \
          "=r"((r)[12]), "=r"((r)[13]), "=r"((r)[14]), "=r"((r)[15]), \
          "=r"((r)[16]), "=r"((r)[17]), "=r"((r)[18]), "=r"((r)[19]), \
          "=r"((r)[20]), "=r"((r)[21]), "=r"((r)[22]), "=r"((r)[23]), \
          "=r"((r)[24]), "=r"((r)[25]), "=r"((r)[26]), "=r"((r)[27]), \
          "=r"((r)[28]), "=r"((r)[29]), "=r"((r)[30]), "=r"((r)[31]) \
        : "r"(ta))

// K-major SW128 SMEM descriptor (LBO=1, SBO=64, version=1, layout SW128)
static constexpr uint64_t SMEM_DESC_BASE_SW128 =
    (uint64_t(2) << 61) | (uint64_t(1) << 46) | (uint64_t(64) << 32) | (uint64_t(1) << 16);
#define MAKE_SMEM_DESC(a) (SMEM_DESC_BASE_SW128 | ((uint64_t)((a) >> 4) & 0x3FFF))

__device__ __forceinline__ uint32_t elect_one_pred() {
    uint32_t p;
    asm volatile("{\n\t.reg .pred p;\n\telect.sync _|p, 0xFFFFFFFF;\n\tselp.b32 %0, 1, 0, p;\n\t}" : "=r"(p));
    return p;
}

// f16 SS MMA, cg1: D[128,256](f32) += A[128,16](f16) * B[256,16](f16)^T
__device__ __forceinline__ void mma_f16_ss(uint32_t d, uint64_t ad, uint64_t bd,
                                           uint32_t idesc, uint32_t en) {
    asm volatile(
        "{\n\t.reg .pred p;\n\tsetp.ne.u32 p, %4, 0;\n\t"
        "tcgen05.mma.cta_group::1.kind::f16 [%0], %1, %2, %3, {%5, %5, %5, %5}, p;\n\t}"
        :: "r"(d), "l"(ad), "l"(bd), "r"(idesc), "r"(en), "r"(0u) : "memory");
}
#endif  // HAS_TC

// CTA tile 128M x 256N, 2-stage pipeline; stage = A 16KB + B 32KB = 48KB.
// smem total 100KB -> 2 CTAs per SM (2x pipelines, overlap epilogues).
static constexpr int SMEM_TILE0   = 4096;
static constexpr int SMEM_STAGE   = 49152;
static constexpr int NSTAGE       = 2;
static constexpr int SMEM_TOTAL_G = SMEM_TILE0 + NSTAGE * SMEM_STAGE;  // 102400

// STAGE 1: h[aid] = fp16(relu(x[tok] @ W1^T + b1))     (K=1024, N=4096)
// STAGE 2: oscr[aid] = fp16((h[aid] @ W2^T + b2)*gate) (K=4096, N=1024)
template <int STAGE>
__global__ void __launch_bounds__(288, 2)
moe_gemm_tc(const float* __restrict__ bias) {
#if HAS_TC
    constexpr int KD  = (STAGE == 1) ? DDIM : HDIM;
    constexpr int ND  = (STAGE == 1) ? HDIM : DDIM;
    constexpr int NCH = KD / 64;                      // 64 halves per chunk
    // kind::f16: dtype F32 (bit4), atype/btype FP16 (=0), N=256, M=128
    constexpr uint32_t IDESC =
        (1u << 4) | ((256u / 8) << 17) | ((128u / 16) << 24);

    extern __shared__ char smem[];
    const uint32_t sb = smem_u32(smem);

    const int slot = blockIdx.y;
    if (slot >= g_ntile) return;                      // compact: few empties
    const int e   = g_tile_e [slot];
    const int m0  = g_tile_m0[slot];
    const int cnt = g_count[e];
    const int n0  = blockIdx.x * 256;

    int*   s_src  = (int*)  (smem + 64);              // [128]
    int*   s_dst  = (int*)  (smem + 64 + 512);        // [128]
    float* s_gate = (float*)(smem + 64 + 1024);       // [128]
    float* s_bias = (float*)(smem + 64 + 1536);       // [256]

    const int tid = threadIdx.x, wid = tid >> 5, lid = tid & 31;

    for (int i = tid; i < 128; i += 288) {
        int cs = min(m0 + i, cnt - 1);
        s_src[i]  = (STAGE == 1) ? g_tok[e][cs] : g_aid[e][cs];
        s_dst[i]  = g_aid[e][cs];
        s_gate[i] = g_gate[e][cs];
    }
    for (int i = tid; i < 256; i += 288) s_bias[i] = bias[e * ND + n0 + i];
    if (tid == 0) {
        for (int s = 0; s < NSTAGE; s++) {
            MBARRIER_INIT(sb + 8  + s * 8, 128);  // full: 128 producer arrivals
            MBARRIER_INIT(sb + 24 + s * 8, 1);    // empty: 1 commit arrival
        }
        MBARRIER_INIT(sb + 40, 1);                // mma done
    }
    if (wid == 8) TCGEN05_ALLOC(sb, 256);
    __syncthreads();

    uint32_t tmem;
    asm volatile("ld.shared.b32 %0, [%1];" : "=r"(tmem) : "r"(sb));

    if (wid >= 4 && wid < 8) {
        // ---- producers: 128 gathered A rows + 256 dense B rows -------------
        const int p   = tid - 128;                // 0..127
        const int c16 = p & 7;                    // 16B column within 128B row
        const int rb  = p >> 3;                   // 0..15
        const __half* Asrc = (STAGE == 1) ? g_xh : g_hscr;
        const __half* Bsrc = (STAGE == 1) ? (g_w1t + (size_t)e * HDIM * DDIM)
                                          : (g_w2t + (size_t)e * DDIM * HDIM);
        // swizzle term identical for all rows rb+i*16 (16 = 0 mod 8)
        const uint32_t sw = (uint32_t)((c16 * 16) ^ ((rb & 7) << 4));
        const uint32_t daB = rb * 128 + sw;               // A dst base
        const uint32_t dbB = 16384 + rb * 128 + sw;       // B dst base
        const __half* pa[8];
#pragma unroll
        for (int i = 0; i < 8; i++)
            pa[i] = Asrc + (size_t)s_src[rb + i * 16] * KD + c16 * 8;
        const __half* pbase = Bsrc + (size_t)(n0 + rb) * KD + c16 * 8;

        int st = 0, ph = 1;                       // producer phase starts at 1
        for (int c = 0; c < NCH; c++) {
            MBARRIER_WAIT_PARITY(sb + 24 + st * 8, ph);
            uint32_t base = sb + SMEM_TILE0 + st * SMEM_STAGE;
            int ko = c * 64;                      // 64 halves per chunk
#pragma unroll
            for (int i = 0; i < 8; i++)           // A: 128 rows
                asm volatile("cp.async.cg.shared.global [%0], [%1], 16;"
                             :: "r"(base + daB + i * 2048), "l"(pa[i] + ko));
#pragma unroll
            for (int i = 0; i < 16; i++)          // B: 256 rows, constant stride
                asm volatile("cp.async.cg.shared.global [%0], [%1], 16;"
                             :: "r"(base + dbB + i * 2048),
                                "l"(pbase + (size_t)i * 16 * KD + ko));
            CPASYNC_ARRIVE_NOINC(sb + 8 + st * 8);
            if (++st == NSTAGE) { st = 0; ph ^= 1; }
        }
    } else if (wid == 8) {
        // ---- MMA issuer: one elected thread ----
        if (elect_one_pred()) {
            int st = 0, ph = 0;
            for (int c = 0; c < NCH; c++) {
                MBARRIER_WAIT_PARITY(sb + 8 + st * 8, ph);
                FENCE_PROXY_ASYNC();
                uint32_t aaddr = sb + SMEM_TILE0 + st * SMEM_STAGE;
                uint64_t ad = MAKE_SMEM_DESC(aaddr);
                uint64_t bd = MAKE_SMEM_DESC(aaddr + 16384);
#pragma unroll
                for (int ka = 0; ka < 4; ka++) {  // 4 x K=16 per 128B chunk
                    uint32_t en = (c > 0 || ka > 0) ? 1u : 0u;
                    mma_f16_ss(tmem, ad + ka * 2, bd + ka * 2, IDESC, en);
                }
                TCGEN05_COMMIT(sb + 24 + st * 8);
                if (++st == NSTAGE) { st = 0; ph ^= 1; }
            }
            TCGEN05_COMMIT(sb + 40);
        }
    } else {
        // ---- consumers (warps 0-3): epilogue after MMA completes ----
        MBARRIER_WAIT_PARITY(sb + 40, 0);
        TCGEN05_FENCE_AFTER();
        const int  tr    = wid * 32 + lid;        // 0..127
        const bool valid = (m0 + tr) < cnt;
        const int  drow  = s_dst[tr];
        const float gt   = s_gate[tr];
        __half* hp = g_hscr + (size_t)drow * HDIM + n0;
        __half* fp = g_oscr + (size_t)drow * DDIM + n0;
        for (int cc = 0; cc < 8; cc++) {
            uint32_t r[32];
            TCGEN05_LD_32X32B_X32(r, tmem + cc * 32);
            TCGEN05_WAIT_LD();
            if (valid) {
                if (STAGE == 1) {
#pragma unroll
                    for (int q = 0; q < 32; q += 4) {
                        float t0 = fmaxf(__uint_as_float(r[q+0]) + s_bias[cc*32+q+0], 0.f);
                        float t1 = fmaxf(__uint_as_float(r[q+1]) + s_bias[cc*32+q+1], 0.f);
                        float t2 = fmaxf(__uint_as_float(r[q+2]) + s_bias[cc*32+q+2], 0.f);
                        float t3 = fmaxf(__uint_as_float(r[q+3]) + s_bias[cc*32+q+3], 0.f);
                        __half2 h0 = __floats2half2_rn(t0, t1);
                        __half2 h1 = __floats2half2_rn(t2, t3);
                        *(uint2*)(hp + cc * 32 + q) =
                            make_uint2(*(uint32_t*)&h0, *(uint32_t*)&h1);
                    }
                } else {
#pragma unroll
                    for (int q = 0; q < 32; q += 4) {
                        float t0 = (__uint_as_float(r[q+0]) + s_bias[cc*32+q+0]) * gt;
                        float t1 = (__uint_as_float(r[q+1]) + s_bias[cc*32+q+1]) * gt;
                        float t2 = (__uint_as_float(r[q+2]) + s_bias[cc*32+q+2]) * gt;
                        float t3 = (__uint_as_float(r[q+3]) + s_bias[cc*32+q+3]) * gt;
                        __half2 h0 = __floats2half2_rn(t0, t1);
                        __half2 h1 = __floats2half2_rn(t2, t3);
                        *(uint2*)(fp + cc * 32 + q) =
                            make_uint2(*(uint32_t*)&h0, *(uint32_t*)&h1);
                    }
                }
            }
        }
        TCGEN05_FENCE_BEFORE();
    }

    __syncthreads();
    if (wid == 8) {
        TCGEN05_RELINQ();
        TCGEN05_DEALLOC(tmem, 256);
    }
#else
    (void)bias;   // plain-sm_103 build: empty kernel; fallback does the work
#endif
}

// ============================================================================
// Fallback path: warp-level mma.sync m16n8k16 fp16 (compiles on plain sm_103)
// ============================================================================
template <int STAGE>
__global__ void __launch_bounds__(256)
moe_gemm_fb(const float* __restrict__ bias) {
    if (g_use_tc) return;

    constexpr int KD = (STAGE == 1) ? DDIM : HDIM;
    constexpr int ND = (STAGE == 1) ? HDIM : DDIM;
    constexpr int KT = KD / 16;

    const int e   = blockIdx.z;
    const int cnt = g_count[e];
    const int m0  = blockIdx.y * 128;
    if (m0 >= cnt) return;
    const int n0  = blockIdx.x * 128;

    const __half* X  = (STAGE == 1) ? g_xh : g_hscr;
    const __half* Bw = (STAGE == 1) ? (g_w1t + (size_t)e * HDIM * DDIM)
                                    : (g_w2t + (size_t)e * DDIM * HDIM);

    __shared__ unsigned As[2][128 * 9];
    __shared__ unsigned Bs[2][128 * 9];
    __shared__ int   s_src[128];
    __shared__ int   s_dst[128];
    __shared__ float s_gate[128];
    __shared__ float s_bias[128];

    const int tid = threadIdx.x;
    for (int i = tid; i < 128; i += 256) {
        int cs = min(m0 + i, cnt - 1);
        s_src[i]  = (STAGE == 1) ? g_tok[e][cs] : g_aid[e][cs];
        s_dst[i]  = g_aid[e][cs];
        s_gate[i] = g_gate[e][cs];
        s_bias[i] = bias[e * ND + n0 + i];
    }
    __syncthreads();

    auto fill = [&](int buf, int kt) {
        int row = tid >> 1, h16 = tid & 1;
        cp16(&As[buf][row * 9 + h16 * 4],
             X + (size_t)s_src[row] * KD + kt * 16 + h16 * 8);
        cp16(&Bs[buf][row * 9 + h16 * 4],
             Bw + (size_t)(n0 + row) * KD + kt * 16 + h16 * 8);
        cp_commit();
    };

    fill(0, 0);

    const int lane = tid & 31;
    const int wid  = tid >> 5;
    const int am   = (wid & 3) * 32;
    const int bn   = (wid >> 2) * 64;
    const int g    = lane >> 2;
    const int t    = lane & 3;

    float acc[2][8][4];
#pragma unroll
    for (int mt = 0; mt < 2; mt++)
#pragma unroll
        for (int nt = 0; nt < 8; nt++)
#pragma unroll
            for (int q = 0; q < 4; q++) acc[mt][nt][q] = 0.f;

    int buf = 0;
    for (int kt = 0; kt < KT; ++kt) {
        if (kt + 1 < KT) { fill(buf ^ 1, kt + 1); cp_wait1(); }
        else             { cp_wait0(); }
        __syncthreads();

        unsigned a[2][4], b[8][2];
#pragma unroll
        for (int mt = 0; mt < 2; mt++) {
            int r0 = am + mt * 16 + g;
            a[mt][0] = As[buf][r0 * 9 + t];
            a[mt][1] = As[buf][(r0 + 8) * 9 + t];
            a[mt][2] = As[buf][r0 * 9 + t + 4];
            a[mt][3] = As[buf][(r0 + 8) * 9 + t + 4];
        }
#pragma unroll
        for (int nt = 0; nt < 8; nt++) {
            int rn = bn + nt * 8 + g;
            b[nt][0] = Bs[buf][rn * 9 + t];
            b[nt][1] = Bs[buf][rn * 9 + t + 4];
        }
#pragma unroll
        for (int mt = 0; mt < 2; mt++)
#pragma unroll
            for (int nt = 0; nt < 8; nt++)
                mma16(acc[mt][nt], a[mt], b[nt]);

        __syncthreads();
        buf ^= 1;
    }

#pragma unroll
    for (int mt = 0; mt < 2; mt++) {
#pragma unroll
        for (int nt = 0; nt < 8; nt++) {
            int col = bn + nt * 8 + 2 * t;
#pragma unroll
            for (int half = 0; half < 2; half++) {
                int lrow = am + mt * 16 + g + half * 8;
                if (m0 + lrow < cnt) {
                    float v0 = acc[mt][nt][half * 2 + 0] + s_bias[col];
                    float v1 = acc[mt][nt][half * 2 + 1] + s_bias[col + 1];
                    if (STAGE == 1) {
                        __half2 hv = __floats2half2_rn(fmaxf(v0, 0.f), fmaxf(v1, 0.f));
                        *(uint32_t*)(g_hscr + (size_t)s_dst[lrow] * HDIM + n0 + col) =
                            *(uint32_t*)&hv;
                    } else {
                        float gg = s_gate[lrow];
                        __half2 hv = __floats2half2_rn(v0 * gg, v1 * gg);
                        *(uint32_t*)(g_oscr + (size_t)s_dst[lrow] * DDIM + n0 + col) =
                            *(uint32_t*)&hv;
                    }
                }
            }
        }
    }
}

// ---------------- combine the two per-token slots (fp16 -> fp32) -------------
__global__ void combine_kernel(float4* __restrict__ out) {
    int i = blockIdx.x * blockDim.x + threadIdx.x;
    int stride = gridDim.x * blockDim.x;
    const int n4 = TTOK * DDIM / 4;
    for (; i < n4; i += stride) {
        int t = i >> 8;            // DDIM/4 = 256
        int c = i & 255;
        uint2 ua = *(const uint2*)(g_oscr + (size_t)(2 * t) * DDIM + c * 4);
        uint2 ub = *(const uint2*)(g_oscr + (size_t)(2 * t + 1) * DDIM + c * 4);
        float2 a0 = __half22float2(*(__half2*)&ua.x);
        float2 a1 = __half22float2(*(__half2*)&ua.y);
        float2 b0 = __half22float2(*(__half2*)&ub.x);
        float2 b1 = __half22float2(*(__half2*)&ub.y);
        out[i] = make_float4(a0.x + b0.x, a0.y + b0.y, a1.x + b1.x, a1.y + b1.y);
    }
}

// ---------------- launcher ---------------------------------------------------
extern "C" void kernel_launch(void* const* d_in, const int* in_sizes, int n_in,
                              void* d_out, int out_size) {
    const float* x      = (const float*)d_in[0];   // [4,2048,1024]
    const float* logits = (const float*)d_in[1];   // [4,2048,8]
    const float* noise  = (const float*)d_in[2];   // [4,2048,8]
    const float* W1     = (const float*)d_in[3];   // [8,1024,4096]
    const float* b1     = (const float*)d_in[4];   // [8,4096]
    const float* W2     = (const float*)d_in[5];   // [8,4096,1024]
    const float* b2     = (const float*)d_in[6];   // [8,1024]
    float* out          = (float*)d_out;           // [4,2048,1024]
    (void)in_sizes; (void)n_in; (void)out_size;

    static __half* w1t_p = nullptr;
    static __half* w2t_p = nullptr;
    if (!w1t_p) { cudaGetSymbolAddress((void**)&w1t_p, g_w1t);
                  cudaGetSymbolAddress((void**)&w2t_p, g_w2t); }

    cudaFuncSetAttribute(moe_gemm_tc<1>, cudaFuncAttributeMaxDynamicSharedMemorySize, SMEM_TOTAL_G);
    cudaFuncSetAttribute(moe_gemm_tc<2>, cudaFuncAttributeMaxDynamicSharedMemorySize, SMEM_TOTAL_G);

    init_kernel<<<1, 32>>>();
    // fused prep: router + round_x + transpose(W1) + transpose(W2) in ONE launch
    prep_kernel<<<PREP_TOTAL, 256>>>((const float4*)x, logits, noise,
                                     W1, W2, w1t_p, w2t_p);
    tilelist_kernel<<<1, 32>>>();

    // GEMM1: 128x256 tiles, 2 CTAs/SM (<= ~136 active slots x 16 N-tiles)
    moe_gemm_tc<1><<<dim3(HDIM / 256, MAXTILE, 1), 288, SMEM_TOTAL_G>>>(b1);
    moe_gemm_fb<1><<<dim3(HDIM / 128, TTOK / 128, NEXP), 256>>>(b1);
    // GEMM2: 128x256 tiles, 2 CTAs/SM (<= ~136 active slots x 4 N-tiles)
    moe_gemm_tc<2><<<dim3(DDIM / 256, MAXTILE, 1), 288, SMEM_TOTAL_G>>>(b2);
    moe_gemm_fb<2><<<dim3(DDIM / 128, TTOK / 128, NEXP), 256>>>(b2);

    combine_kernel<<<1024, 256>>>((float4*)out);
}

// round 15
// speedup vs baseline: 1.3093x; 1.3093x over previous
#include <cuda_runtime.h>
#include <cuda_fp16.h>
#include <cstdint>

#define TTOK 8192
#define DDIM 1024
#define HDIM 4096
#define NEXP 8
#define MAXTILE 72

// prep_kernel block-range dispatch (router first so its latency hides under
// the bandwidth-bound transposes)
#define PREP_RT 32
#define PREP_RX 512
#define PREP_W1 8192
#define PREP_W2 8192
#define PREP_TOTAL (PREP_RT + PREP_RX + PREP_W1 + PREP_W2)

// a-feature availability for the CURRENT compilation target
#if defined(__CUDA_ARCH_FEAT_SM103_ALL) || defined(__CUDA_ARCH_FEAT_SM100_ALL)
#define HAS_TC 1
#else
#define HAS_TC 0
#endif

// ---------------- scratch (device globals; no runtime allocation) -----------
__device__ int    g_use_tc;
__device__ int    g_count[NEXP];
__device__ int    g_tok [NEXP][TTOK];
__device__ int    g_aid [NEXP][TTOK];
__device__ float  g_gate[NEXP][TTOK];
__device__ int    g_tile_e [80];                          // flat M-tile list
__device__ int    g_tile_m0[80];
__device__ int    g_ntile;
__device__ __half g_xh  [(size_t)TTOK * DDIM];            //  16 MB fp16 x
__device__ __half g_w1t [(size_t)NEXP * HDIM * DDIM];     //  64 MB W1^T fp16 (K-major)
__device__ __half g_w2t [(size_t)NEXP * DDIM * HDIM];     //  64 MB W2^T fp16 (K-major)
__device__ __half g_hscr[(size_t)2 * TTOK * HDIM];        // 134 MB h by aid (fp16)
__device__ __half g_oscr[(size_t)2 * TTOK * DDIM];        //  34 MB per-slot out (fp16)

// ---------------- small helpers ---------------------------------------------
__device__ __forceinline__ uint32_t smem_u32(const void* p) {
    uint32_t a;
    asm("{ .reg .u64 t; cvta.to.shared.u64 t, %1; cvt.u32.u64 %0, t; }" : "=r"(a) : "l"(p));
    return a;
}
__device__ __forceinline__ void cp16(void* dst, const void* src) {
    unsigned s = (unsigned)__cvta_generic_to_shared(dst);
    asm volatile("cp.async.cg.shared.global [%0], [%1], 16;" :: "r"(s), "l"(src));
}
__device__ __forceinline__ void cp_commit() { asm volatile("cp.async.commit_group;"); }
__device__ __forceinline__ void cp_wait1()  { asm volatile("cp.async.wait_group 1;"); }
__device__ __forceinline__ void cp_wait0()  { asm volatile("cp.async.wait_group 0;"); }

// fp16 mma.sync m16n8k16, fp32 accumulate (fallback path)
__device__ __forceinline__ void mma16(float* c, const unsigned* a, const unsigned* b) {
    asm volatile(
        "mma.sync.aligned.m16n8k16.row.col.f32.f16.f16.f32 "
        "{%0,%1,%2,%3}, {%4,%5,%6,%7}, {%8,%9}, {%0,%1,%2,%3};"
        : "+f"(c[0]), "+f"(c[1]), "+f"(c[2]), "+f"(c[3])
        : "r"(a[0]), "r"(a[1]), "r"(a[2]), "r"(a[3]), "r"(b[0]), "r"(b[1]));
}

// ---------------- init (probe + zero counts) ---------------------------------
__global__ void init_kernel() {
    if (threadIdx.x == 0) g_use_tc = HAS_TC;
    if (threadIdx.x < NEXP) g_count[threadIdx.x] = 0;
}

// ---------------- fused prep: router + round_x + both W transposes ----------
// One launch; each block takes exactly one uniform branch on blockIdx.x.
// Router (latency-bound) and round_x ride for free under the bandwidth-bound
// transposes. All four tasks are mutually independent.
__global__ void __launch_bounds__(256)
prep_kernel(const float4* __restrict__ x,
            const float*  __restrict__ logits,
            const float*  __restrict__ noise,
            const float*  __restrict__ W1,
            const float*  __restrict__ W2,
            __half* __restrict__ w1t,
            __half* __restrict__ w2t) {
    __shared__ float ts[64][65];
    const int bid = blockIdx.x;

    if (bid < PREP_RT) {
        // ---- router: noisy top-2 + gates + expert lists (vectorized loads) --
        int t = bid * 256 + threadIdx.x;
        if (t >= TTOK) return;
        float4 L0 = *(const float4*)(logits + (size_t)t * NEXP);
        float4 L1 = *(const float4*)(logits + (size_t)t * NEXP + 4);
        float4 N0 = *(const float4*)(noise  + (size_t)t * NEXP);
        float4 N1 = *(const float4*)(noise  + (size_t)t * NEXP + 4);
        float l [8] = {L0.x, L0.y, L0.z, L0.w, L1.x, L1.y, L1.z, L1.w};
        float nz[8] = {N0.x, N0.y, N0.z, N0.w, N1.x, N1.y, N1.z, N1.w};

        float v0 = -1e30f, v1 = -1e30f;
        int i0 = 0, i1 = 0;
#pragma unroll
        for (int e = 0; e < NEXP; e++) {
            float sp = fmaxf(l[e], 0.f) + log1pf(expf(-fabsf(l[e])));
            float v  = l[e] + nz[e] * sp;
            if (v > v0)      { v1 = v0; i1 = i0; v0 = v; i0 = e; }
            else if (v > v1) { v1 = v;  i1 = e; }
        }
        float e1  = expf(v1 - v0);
        float den = 1.f + e1;
        float ga  = 1.f / den;
        float gb  = e1 / den;

        int s0 = atomicAdd(&g_count[i0], 1);
        g_tok[i0][s0] = t; g_aid[i0][s0] = 2 * t;     g_gate[i0][s0] = ga;
        int s1 = atomicAdd(&g_count[i1], 1);
        g_tok[i1][s1] = t; g_aid[i1][s1] = 2 * t + 1; g_gate[i1][s1] = gb;

    } else if (bid < PREP_RT + PREP_RX) {
        // ---- round_x: fp32 x -> fp16 (RNE), grid-stride --------------------
        int b = bid - PREP_RT;
        int i = b * 256 + threadIdx.x;
        const int stride = PREP_RX * 256;
        const int n4 = TTOK * DDIM / 4;
        for (; i < n4; i += stride) {
            float4 v = x[i];
            __half2 h0 = __floats2half2_rn(v.x, v.y);
            __half2 h1 = __floats2half2_rn(v.z, v.w);
            *(uint2*)(g_xh + (size_t)i * 4) =
                make_uint2(*(uint32_t*)&h0, *(uint32_t*)&h1);
        }

    } else {
        // ---- weight transpose + round: in[e][R][C] -> out[e][C][R] fp16 ----
        const float* in; __half* out; int R, C, bx, by, bz;
        if (bid < PREP_RT + PREP_RX + PREP_W1) {
            int b = bid - (PREP_RT + PREP_RX);
            in = W1; out = w1t; R = DDIM; C = HDIM;
            bx = b % (HDIM / 64);
            int r = b / (HDIM / 64);
            by = r % (DDIM / 64);
            bz = r / (DDIM / 64);
        } else {
            int b = bid - (PREP_RT + PREP_RX + PREP_W1);
            in = W2; out = w2t; R = HDIM; C = DDIM;
            bx = b % (DDIM / 64);
            int r = b / (DDIM / 64);
            by = r % (HDIM / 64);
            bz = r / (HDIM / 64);
        }
        size_t base = (size_t)bz * R * C;
        int c0 = bx * 64, r0 = by * 64;
        int tx = threadIdx.x & 15;          // float4 column
        int ty = threadIdx.x >> 4;          // row group
#pragma unroll
        for (int j = 0; j < 4; j++) {
            int row = ty + j * 16;
            float4 v = *(const float4*)(in + base + (size_t)(r0 + row) * C + c0 + tx * 4);
            ts[row][tx * 4 + 0] = v.x;
            ts[row][tx * 4 + 1] = v.y;
            ts[row][tx * 4 + 2] = v.z;
            ts[row][tx * 4 + 3] = v.w;
        }
        __syncthreads();
#pragma unroll
        for (int j = 0; j < 4; j++) {
            int oc = ty + j * 16;           // output row = original column
            __half2 h0 = __floats2half2_rn(ts[tx * 4 + 0][oc], ts[tx * 4 + 1][oc]);
            __half2 h1 = __floats2half2_rn(ts[tx * 4 + 2][oc], ts[tx * 4 + 3][oc]);
            *(uint2*)(out + base + (size_t)(c0 + oc) * R + r0 + tx * 4) =
                make_uint2(*(uint32_t*)&h0, *(uint32_t*)&h1);
        }
    }
}

// ---------------- flat M-tile list (compact grids, no empty-CTA waves) -------
__global__ void tilelist_kernel() {
    if (threadIdx.x != 0) return;
    int n = 0;
    for (int e = 0; e < NEXP; e++) {
        int cnt = g_count[e];
        for (int m0 = 0; m0 < cnt; m0 += 256) {
            g_tile_e [n] = e;
            g_tile_m0[n] = m0;
            n++;
        }
    }
    g_ntile = n;                       // <= 71 since sum(cnt) = 2*TTOK
}

// ============================================================================
// tcgen05 path (compiled only for sm_103a/sm_100a targets) — cg1 256x256 fp16
// ============================================================================
#if HAS_TC

#define MBARRIER_INIT(addr, cnt) \
    asm volatile("mbarrier.init.shared.b64 [%0], %1;" :: "r"((uint32_t)(addr)), "r"((uint32_t)(cnt)) : "memory")

#define MBARRIER_WAIT_PARITY(mbar, par) do {                                            \
    uint32_t _m = (uint32_t)(mbar), _p = (uint32_t)(par), _d;                           \
    asm volatile("{\n\t.reg .pred p;\n\t"                                               \
        "mbarrier.try_wait.parity.acquire.cta.shared::cta.b64 p, [%1], %2;\n\t"         \
        "selp.b32 %0, 1, 0, p;\n\t}" : "=r"(_d) : "r"(_m), "r"(_p) : "memory");         \
    if (!_d) {                                                                          \
        asm volatile("{\n\t.reg .pred P1;\n\tWL_%=:\n\t"                                \
            "mbarrier.try_wait.parity.acquire.cta.shared::cta.b64 P1, [%0], %1, 0x989680;\n\t" \
            "@P1 bra.uni WD_%=;\n\tbra.uni WL_%=;\n\tWD_%=:\n\t}"                       \
            :: "r"(_m), "r"(_p) : "memory");                                            \
    }                                                                                   \
} while (0)

#define CPASYNC_ARRIVE_NOINC(mbar) \
    asm volatile("cp.async.mbarrier.arrive.noinc.shared::cta.b64 [%0];" :: "r"((uint32_t)(mbar)) : "memory")

#define TCGEN05_ALLOC(sa, n) \
    asm volatile("tcgen05.alloc.cta_group::1.sync.aligned.shared::cta.b32 [%0], %1;" \
                 :: "r"((uint32_t)(sa)), "r"((uint32_t)(n)) : "memory")
#define TCGEN05_DEALLOC(t, n) \
    asm volatile("tcgen05.dealloc.cta_group::1.sync.aligned.b32 %0, %1;" :: "r"(t), "r"((uint32_t)(n)))
#define TCGEN05_RELINQ() \
    asm volatile("tcgen05.relinquish_alloc_permit.cta_group::1.sync.aligned;")
#define TCGEN05_COMMIT(mbar) \
    asm volatile("tcgen05.commit.cta_group::1.mbarrier::arrive::one.shared::cluster.b64 [%0];" \
                 :: "r"((uint32_t)(mbar)) : "memory")
#define TCGEN05_FENCE_AFTER()  asm volatile("tcgen05.fence::after_thread_sync;" ::: "memory")
#define TCGEN05_FENCE_BEFORE() asm volatile("tcgen05.fence::before_thread_sync;" ::: "memory")
#define TCGEN05_WAIT_LD()      asm volatile("tcgen05.wait::ld.sync.aligned;" ::: "memory")
#define FENCE_PROXY_ASYNC()    asm volatile("fence.proxy.async.shared::cta;" ::: "memory")

#define TCGEN05_LD_32X32B_X32(r, ta) \
    asm volatile( \
        "tcgen05.ld.sync.aligned.32x32b.x32.b32 " \
        "{%0, %1, %2, %3, %4, %5, %6, %7, " \
        " %8, %9, %10, %11, %12, %13, %14, %15, " \
        " %16, %17, %18, %19, %20, %21, %22, %23, " \
        " %24, %25, %26, %27, %28, %29, %30, %31}, [%32];" \
        : "=r"((r)[0]),  "=r"((r)[1]),  "=r"((r)[2]),  "=r"((r)[3]), \
          "=r"((r)[4]),  "=r"((r)[5]),  "=r"((r)[6]),  "=r"((r)[7]), \
          "=r"((r)[8]),  "=r"((r)[9]),  "=r"((r)[10]), "=r"((r)[11]), \
          "=r"((r)[12]), "=r"((r)[13]), "=r"((r)[14]), "=r"((r)[15]), \
          "=r"((r)[16]), "=r"((r)[17]), "=r"((r)[18]), "=r"((r)[19]), \
          "=r"((r)[20]), "=r"((r)[21]), "=r"((r)[22]), "=r"((r)[23]), \
          "=r"((r)[24]), "=r"((r)[25]), "=r"((r)[26]), "=r"((r)[27]), \
          "=r"((r)[28]), "=r"((r)[29]), "=r"((r)[30]), "=r"((r)[31]) \
        : "r"(ta))

// K-major SW128 SMEM descriptor (LBO=1, SBO=64, version=1, layout SW128)
static constexpr uint64_t SMEM_DESC_BASE_SW128 =
    (uint64_t(2) << 61) | (uint64_t(1) << 46) | (uint64_t(64) << 32) | (uint64_t(1) << 16);
#define MAKE_SMEM_DESC(a) (SMEM_DESC_BASE_SW128 | ((uint64_t)((a) >> 4) & 0x3FFF))

__device__ __forceinline__ uint32_t elect_one_pred() {
    uint32_t p;
    asm volatile("{\n\t.reg .pred p;\n\telect.sync _|p, 0xFFFFFFFF;\n\tselp.b32 %0, 1, 0, p;\n\t}" : "=r"(p));
    return p;
}

// f16 SS MMA, cg1: D[128,256](f32) += A[128,16](f16) * B[256,16](f16)^T
__device__ __forceinline__ void mma_f16_ss(uint32_t d, uint64_t ad, uint64_t bd,
                                           uint32_t idesc, uint32_t en) {
    asm volatile(
        "{\n\t.reg .pred p;\n\tsetp.ne.u32 p, %4, 0;\n\t"
        "tcgen05.mma.cta_group::1.kind::f16 [%0], %1, %2, %3, {%5, %5, %5, %5}, p;\n\t}"
        :: "r"(d), "l"(ad), "l"(bd), "r"(idesc), "r"(en), "r"(0u) : "memory");
}
#endif  // HAS_TC

// CTA tile 256M x 256N, 3-stage cp.async pipeline, K-chunk = 64 halves (128B)
static constexpr int SMEM_TILE0   = 5120;
static constexpr int SMEM_STAGE   = 65536;            // A 32KB + B 32KB
static constexpr int SMEM_TOTAL_G = SMEM_TILE0 + 3 * SMEM_STAGE;  // 201728

// STAGE 1: h[aid] = fp16(relu(x[tok] @ W1^T + b1))     (K=1024, N=4096)
// STAGE 2: oscr[aid] = fp16((h[aid] @ W2^T + b2)*gate) (K=4096, N=1024)
template <int STAGE>
__global__ void __launch_bounds__(288, 1)
moe_gemm_tc(const float* __restrict__ bias) {
#if HAS_TC
    constexpr int KD  = (STAGE == 1) ? DDIM : HDIM;
    constexpr int ND  = (STAGE == 1) ? HDIM : DDIM;
    constexpr int NCH = KD / 64;                      // 64 halves per chunk
    // kind::f16: dtype F32 (bit4), atype/btype FP16 (=0), N=256, M=128
    constexpr uint32_t IDESC =
        (1u << 4) | ((256u / 8) << 17) | ((128u / 16) << 24);

    extern __shared__ char smem[];
    const uint32_t sb = smem_u32(smem);

    const int slot = blockIdx.y;
    if (slot >= g_ntile) return;                      // compact: few empties
    const int e   = g_tile_e [slot];
    const int m0  = g_tile_m0[slot];
    const int cnt = g_count[e];
    const int n0  = blockIdx.x * 256;

    int*   s_src  = (int*)  (smem + 64);
    int*   s_dst  = (int*)  (smem + 64 + 1024);
    float* s_gate = (float*)(smem + 64 + 2048);
    float* s_bias = (float*)(smem + 64 + 3072);

    const int tid = threadIdx.x, wid = tid >> 5, lid = tid & 31;

    for (int i = tid; i < 256; i += 288) {
        int cs = min(m0 + i, cnt - 1);
        s_src[i]  = (STAGE == 1) ? g_tok[e][cs] : g_aid[e][cs];
        s_dst[i]  = g_aid[e][cs];
        s_gate[i] = g_gate[e][cs];
        s_bias[i] = bias[e * ND + n0 + i];
    }
    if (tid == 0) {
        for (int s = 0; s < 3; s++) {
            MBARRIER_INIT(sb + 8  + s * 8, 128);  // full: 128 producer arrivals
            MBARRIER_INIT(sb + 32 + s * 8, 1);    // empty: 1 commit arrival
        }
        MBARRIER_INIT(sb + 56, 1);                // mma done
    }
    if (wid == 8) TCGEN05_ALLOC(sb, 512);
    __syncthreads();

    uint32_t tmem;
    asm volatile("ld.shared.b32 %0, [%1];" : "=r"(tmem) : "r"(sb));

    if (wid >= 4 && wid < 8) {
        // ---- producers: gathered A rows + dense B rows, cp.async + SW128 ----
        const int p   = tid - 128;                // 0..127
        const int c16 = p & 7;                    // 16B column within 128B row
        const int rb  = p >> 3;
        const __half* Asrc = (STAGE == 1) ? g_xh : g_hscr;
        const __half* Bsrc = (STAGE == 1) ? (g_w1t + (size_t)e * HDIM * DDIM)
                                          : (g_w2t + (size_t)e * DDIM * HDIM);
        const __half* pa[16];
        const __half* pb[16];
        uint32_t      da[16];
#pragma unroll
        for (int i = 0; i < 16; i++) {
            int row = rb + i * 16;
            pa[i] = Asrc + (size_t)s_src[row] * KD + c16 * 8;     // 8 halves / 16B
            pb[i] = Bsrc + (size_t)(n0 + row) * KD + c16 * 8;
            da[i] = row * 128 + ((c16 * 16) ^ ((row & 7) << 4));  // SW128 bytes
        }
        int st = 0, ph = 1;                       // producer phase starts at 1
        for (int c = 0; c < NCH; c++) {
            MBARRIER_WAIT_PARITY(sb + 32 + st * 8, ph);
            uint32_t base = sb + SMEM_TILE0 + st * SMEM_STAGE;
            int ko = c * 64;                      // 64 halves per chunk
#pragma unroll
            for (int i = 0; i < 16; i++)
                asm volatile("cp.async.cg.shared.global [%0], [%1], 16;"
                             :: "r"(base + da[i]), "l"(pa[i] + ko));
#pragma unroll
            for (int i = 0; i < 16; i++)
                asm volatile("cp.async.cg.shared.global [%0], [%1], 16;"
                             :: "r"(base + 32768 + da[i]), "l"(pb[i] + ko));
            CPASYNC_ARRIVE_NOINC(sb + 8 + st * 8);
            if (++st == 3) { st = 0; ph ^= 1; }
        }
    } else if (wid == 8) {
        // ---- MMA issuer: one elected thread ----
        if (elect_one_pred()) {
            int st = 0, ph = 0;
            for (int c = 0; c < NCH; c++) {
                MBARRIER_WAIT_PARITY(sb + 8 + st * 8, ph);
                FENCE_PROXY_ASYNC();
                uint32_t aaddr = sb + SMEM_TILE0 + st * SMEM_STAGE;
                uint64_t ad = MAKE_SMEM_DESC(aaddr);
                uint64_t bd = MAKE_SMEM_DESC(aaddr + 32768);
#pragma unroll
                for (int ka = 0; ka < 4; ka++) {  // 4 x K=16 per 128B chunk
                    uint32_t en = (c > 0 || ka > 0) ? 1u : 0u;
                    mma_f16_ss(tmem,       ad + ka * 2,        bd + ka * 2, IDESC, en);
                    mma_f16_ss(tmem + 256, ad + 1024 + ka * 2, bd + ka * 2, IDESC, en);
                }
                TCGEN05_COMMIT(sb + 32 + st * 8);
                if (++st == 3) { st = 0; ph ^= 1; }
            }
            TCGEN05_COMMIT(sb + 56);
        }
    } else {
        // ---- consumers (warps 0-3): epilogue after MMA completes ----
        MBARRIER_WAIT_PARITY(sb + 56, 0);
        TCGEN05_FENCE_AFTER();
#pragma unroll
        for (int mh = 0; mh < 2; mh++) {
            int  tr    = mh * 128 + wid * 32 + lid;
            bool valid = (m0 + tr) < cnt;
            int  drow  = s_dst[tr];
            float gt   = s_gate[tr];
            __half* hp = g_hscr + (size_t)drow * HDIM + n0;
            __half* fp = g_oscr + (size_t)drow * DDIM + n0;
            for (int cc = 0; cc < 8; cc++) {
                uint32_t r[32];
                TCGEN05_LD_32X32B_X32(r, tmem + mh * 256 + cc * 32);
                TCGEN05_WAIT_LD();
                if (valid) {
                    if (STAGE == 1) {
#pragma unroll
                        for (int q = 0; q < 32; q += 4) {
                            float t0 = fmaxf(__uint_as_float(r[q+0]) + s_bias[cc*32+q+0], 0.f);
                            float t1 = fmaxf(__uint_as_float(r[q+1]) + s_bias[cc*32+q+1], 0.f);
                            float t2 = fmaxf(__uint_as_float(r[q+2]) + s_bias[cc*32+q+2], 0.f);
                            float t3 = fmaxf(__uint_as_float(r[q+3]) + s_bias[cc*32+q+3], 0.f);
                            __half2 h0 = __floats2half2_rn(t0, t1);
                            __half2 h1 = __floats2half2_rn(t2, t3);
                            *(uint2*)(hp + cc * 32 + q) =
                                make_uint2(*(uint32_t*)&h0, *(uint32_t*)&h1);
                        }
                    } else {
#pragma unroll
                        for (int q = 0; q < 32; q += 4) {
                            float t0 = (__uint_as_float(r[q+0]) + s_bias[cc*32+q+0]) * gt;
                            float t1 = (__uint_as_float(r[q+1]) + s_bias[cc*32+q+1]) * gt;
                            float t2 = (__uint_as_float(r[q+2]) + s_bias[cc*32+q+2]) * gt;
                            float t3 = (__uint_as_float(r[q+3]) + s_bias[cc*32+q+3]) * gt;
                            __half2 h0 = __floats2half2_rn(t0, t1);
                            __half2 h1 = __floats2half2_rn(t2, t3);
                            *(uint2*)(fp + cc * 32 + q) =
                                make_uint2(*(uint32_t*)&h0, *(uint32_t*)&h1);
                        }
                    }
                }
            }
        }
        TCGEN05_FENCE_BEFORE();
    }

    __syncthreads();
    if (wid == 8) {
        TCGEN05_RELINQ();
        TCGEN05_DEALLOC(tmem, 512);
    }
#else
    (void)bias;   // plain-sm_103 build: empty kernel; fallback does the work
#endif
}

// ============================================================================
// Fallback path: warp-level mma.sync m16n8k16 fp16 (compiles on plain sm_103)
// ============================================================================
template <int STAGE>
__global__ void __launch_bounds__(256)
moe_gemm_fb(const float* __restrict__ bias) {
    if (g_use_tc) return;

    constexpr int KD = (STAGE == 1) ? DDIM : HDIM;
    constexpr int ND = (STAGE == 1) ? HDIM : DDIM;
    constexpr int KT = KD / 16;

    const int e   = blockIdx.z;
    const int cnt = g_count[e];
    const int m0  = blockIdx.y * 128;
    if (m0 >= cnt) return;
    const int n0  = blockIdx.x * 128;

    const __half* X  = (STAGE == 1) ? g_xh : g_hscr;
    const __half* Bw = (STAGE == 1) ? (g_w1t + (size_t)e * HDIM * DDIM)
                                    : (g_w2t + (size_t)e * DDIM * HDIM);

    __shared__ unsigned As[2][128 * 9];
    __shared__ unsigned Bs[2][128 * 9];
    __shared__ int   s_src[128];
    __shared__ int   s_dst[128];
    __shared__ float s_gate[128];
    __shared__ float s_bias[128];

    const int tid = threadIdx.x;
    for (int i = tid; i < 128; i += 256) {
        int cs = min(m0 + i, cnt - 1);
        s_src[i]  = (STAGE == 1) ? g_tok[e][cs] : g_aid[e][cs];
        s_dst[i]  = g_aid[e][cs];
        s_gate[i] = g_gate[e][cs];
        s_bias[i] = bias[e * ND + n0 + i];
    }
    __syncthreads();

    auto fill = [&](int buf, int kt) {
        int row = tid >> 1, h16 = tid & 1;
        cp16(&As[buf][row * 9 + h16 * 4],
             X + (size_t)s_src[row] * KD + kt * 16 + h16 * 8);
        cp16(&Bs[buf][row * 9 + h16 * 4],
             Bw + (size_t)(n0 + row) * KD + kt * 16 + h16 * 8);
        cp_commit();
    };

    fill(0, 0);

    const int lane = tid & 31;
    const int wid  = tid >> 5;
    const int am   = (wid & 3) * 32;
    const int bn   = (wid >> 2) * 64;
    const int g    = lane >> 2;
    const int t    = lane & 3;

    float acc[2][8][4];
#pragma unroll
    for (int mt = 0; mt < 2; mt++)
#pragma unroll
        for (int nt = 0; nt < 8; nt++)
#pragma unroll
            for (int q = 0; q < 4; q++) acc[mt][nt][q] = 0.f;

    int buf = 0;
    for (int kt = 0; kt < KT; ++kt) {
        if (kt + 1 < KT) { fill(buf ^ 1, kt + 1); cp_wait1(); }
        else             { cp_wait0(); }
        __syncthreads();

        unsigned a[2][4], b[8][2];
#pragma unroll
        for (int mt = 0; mt < 2; mt++) {
            int r0 = am + mt * 16 + g;
            a[mt][0] = As[buf][r0 * 9 + t];
            a[mt][1] = As[buf][(r0 + 8) * 9 + t];
            a[mt][2] = As[buf][r0 * 9 + t + 4];
            a[mt][3] = As[buf][(r0 + 8) * 9 + t + 4];
        }
#pragma unroll
        for (int nt = 0; nt < 8; nt++) {
            int rn = bn + nt * 8 + g;
            b[nt][0] = Bs[buf][rn * 9 + t];
            b[nt][1] = Bs[buf][rn * 9 + t + 4];
        }
#pragma unroll
        for (int mt = 0; mt < 2; mt++)
#pragma unroll
            for (int nt = 0; nt < 8; nt++)
                mma16(acc[mt][nt], a[mt], b[nt]);

        __syncthreads();
        buf ^= 1;
    }

#pragma unroll
    for (int mt = 0; mt < 2; mt++) {
#pragma unroll
        for (int nt = 0; nt < 8; nt++) {
            int col = bn + nt * 8 + 2 * t;
#pragma unroll
            for (int half = 0; half < 2; half++) {
                int lrow = am + mt * 16 + g + half * 8;
                if (m0 + lrow < cnt) {
                    float v0 = acc[mt][nt][half * 2 + 0] + s_bias[col];
                    float v1 = acc[mt][nt][half * 2 + 1] + s_bias[col + 1];
                    if (STAGE == 1) {
                        __half2 hv = __floats2half2_rn(fmaxf(v0, 0.f), fmaxf(v1, 0.f));
                        *(uint32_t*)(g_hscr + (size_t)s_dst[lrow] * HDIM + n0 + col) =
                            *(uint32_t*)&hv;
                    } else {
                        float gg = s_gate[lrow];
                        __half2 hv = __floats2half2_rn(v0 * gg, v1 * gg);
                        *(uint32_t*)(g_oscr + (size_t)s_dst[lrow] * DDIM + n0 + col) =
                            *(uint32_t*)&hv;
                    }
                }
            }
        }
    }
}

// ---------------- combine the two per-token slots (fp16 -> fp32) -------------
__global__ void combine_kernel(float4* __restrict__ out) {
    int i = blockIdx.x * blockDim.x + threadIdx.x;
    int stride = gridDim.x * blockDim.x;
    const int n4 = TTOK * DDIM / 4;
    for (; i < n4; i += stride) {
        int t = i >> 8;            // DDIM/4 = 256
        int c = i & 255;
        uint2 ua = *(const uint2*)(g_oscr + (size_t)(2 * t) * DDIM + c * 4);
        uint2 ub = *(const uint2*)(g_oscr + (size_t)(2 * t + 1) * DDIM + c * 4);
        float2 a0 = __half22float2(*(__half2*)&ua.x);
        float2 a1 = __half22float2(*(__half2*)&ua.y);
        float2 b0 = __half22float2(*(__half2*)&ub.x);
        float2 b1 = __half22float2(*(__half2*)&ub.y);
        out[i] = make_float4(a0.x + b0.x, a0.y + b0.y, a1.x + b1.x, a1.y + b1.y);
    }
}

// ---------------- launcher ---------------------------------------------------
extern "C" void kernel_launch(void* const* d_in, const int* in_sizes, int n_in,
                              void* d_out, int out_size) {
    const float* x      = (const float*)d_in[0];   // [4,2048,1024]
    const float* logits = (const float*)d_in[1];   // [4,2048,8]
    const float* noise  = (const float*)d_in[2];   // [4,2048,8]
    const float* W1     = (const float*)d_in[3];   // [8,1024,4096]
    const float* b1     = (const float*)d_in[4];   // [8,4096]
    const float* W2     = (const float*)d_in[5];   // [8,4096,1024]
    const float* b2     = (const float*)d_in[6];   // [8,1024]
    float* out          = (float*)d_out;           // [4,2048,1024]
    (void)in_sizes; (void)n_in; (void)out_size;

    static __half* w1t_p = nullptr;
    static __half* w2t_p = nullptr;
    if (!w1t_p) { cudaGetSymbolAddress((void**)&w1t_p, g_w1t);
                  cudaGetSymbolAddress((void**)&w2t_p, g_w2t); }

    cudaFuncSetAttribute(moe_gemm_tc<1>, cudaFuncAttributeMaxDynamicSharedMemorySize, SMEM_TOTAL_G);
    cudaFuncSetAttribute(moe_gemm_tc<2>, cudaFuncAttributeMaxDynamicSharedMemorySize, SMEM_TOTAL_G);

    init_kernel<<<1, 32>>>();
    // fused prep: router + round_x + transpose(W1) + transpose(W2) in ONE launch
    prep_kernel<<<PREP_TOTAL, 256>>>((const float4*)x, logits, noise,
                                     W1, W2, w1t_p, w2t_p);
    tilelist_kernel<<<1, 32>>>();

    // GEMM1: compact flat-tile grid (<= ~71 active slots x 16 N-tiles)
    moe_gemm_tc<1><<<dim3(HDIM / 256, MAXTILE, 1), 288, SMEM_TOTAL_G>>>(b1);
    moe_gemm_fb<1><<<dim3(HDIM / 128, TTOK / 128, NEXP), 256>>>(b1);
    // GEMM2: compact flat-tile grid (<= ~71 active slots x 4 N-tiles)
    moe_gemm_tc<2><<<dim3(DDIM / 256, MAXTILE, 1), 288, SMEM_TOTAL_G>>>(b2);
    moe_gemm_fb<2><<<dim3(DDIM / 128, TTOK / 128, NEXP), 256>>>(b2);

    combine_kernel<<<1024, 256>>>((float4*)out);
}

// round 16
// speedup vs baseline: 1.3293x; 1.0153x over previous
#include <cuda_runtime.h>
#include <cuda_fp16.h>
#include <cstdint>

#define TTOK 8192
#define DDIM 1024
#define HDIM 4096
#define NEXP 8
#define MAXTILE 72

// prep_kernel block-range dispatch
#define PREP_RT 32
#define PREP_RX 512
#define PREP_W1 8192
#define PREP_W2 8192
#define PREP_TOTAL (PREP_RT + PREP_RX + PREP_W1 + PREP_W2)

// a-feature availability for the CURRENT compilation target
#if defined(__CUDA_ARCH_FEAT_SM103_ALL) || defined(__CUDA_ARCH_FEAT_SM100_ALL)
#define HAS_TC 1
#else
#define HAS_TC 0
#endif

// ---------------- scratch (device globals; no runtime allocation) -----------
__device__ int    g_use_tc;
__device__ int    g_count[NEXP];
__device__ int    g_tok [NEXP][TTOK];
__device__ int    g_aid [NEXP][TTOK];
__device__ float  g_gate[NEXP][TTOK];
__device__ int    g_tile_e [80];                          // flat M-tile list
__device__ int    g_tile_m0[80];
__device__ int    g_ntile;
__device__ __half g_xh  [(size_t)TTOK * DDIM];            //  16 MB fp16 x
__device__ __half g_w1t [(size_t)NEXP * HDIM * DDIM];     //  64 MB W1^T fp16 (K-major)
__device__ __half g_w2t [(size_t)NEXP * DDIM * HDIM];     //  64 MB W2^T fp16 (K-major)
__device__ __half g_hscr[(size_t)2 * TTOK * HDIM];        // 134 MB h by aid (fp16)
__device__ __half g_oscr[(size_t)2 * TTOK * DDIM];        //  34 MB per-slot out (fp16)

// ---------------- small helpers ---------------------------------------------
__device__ __forceinline__ uint32_t smem_u32(const void* p) {
    uint32_t a;
    asm("{ .reg .u64 t; cvta.to.shared.u64 t, %1; cvt.u32.u64 %0, t; }" : "=r"(a) : "l"(p));
    return a;
}
__device__ __forceinline__ void cp16(void* dst, const void* src) {
    unsigned s = (unsigned)__cvta_generic_to_shared(dst);
    asm volatile("cp.async.cg.shared.global [%0], [%1], 16;" :: "r"(s), "l"(src));
}
__device__ __forceinline__ void cp_commit() { asm volatile("cp.async.commit_group;"); }
__device__ __forceinline__ void cp_wait1()  { asm volatile("cp.async.wait_group 1;"); }
__device__ __forceinline__ void cp_wait0()  { asm volatile("cp.async.wait_group 0;"); }

// fp16 mma.sync m16n8k16, fp32 accumulate (fallback path)
__device__ __forceinline__ void mma16(float* c, const unsigned* a, const unsigned* b) {
    asm volatile(
        "mma.sync.aligned.m16n8k16.row.col.f32.f16.f16.f32 "
        "{%0,%1,%2,%3}, {%4,%5,%6,%7}, {%8,%9}, {%0,%1,%2,%3};"
        : "+f"(c[0]), "+f"(c[1]), "+f"(c[2]), "+f"(c[3])
        : "r"(a[0]), "r"(a[1]), "r"(a[2]), "r"(a[3]), "r"(b[0]), "r"(b[1]));
}

// ---------------- init (probe + zero counts) ---------------------------------
__global__ void init_kernel() {
    if (threadIdx.x == 0) g_use_tc = HAS_TC;
    if (threadIdx.x < NEXP) g_count[threadIdx.x] = 0;
}

// ---------------- fused prep: router + round_x + both W transposes ----------
__global__ void __launch_bounds__(256)
prep_kernel(const float4* __restrict__ x,
            const float*  __restrict__ logits,
            const float*  __restrict__ noise,
            const float*  __restrict__ W1,
            const float*  __restrict__ W2,
            __half* __restrict__ w1t,
            __half* __restrict__ w2t) {
    __shared__ float ts[64][65];
    const int bid = blockIdx.x;

    if (bid < PREP_RT) {
        // ---- router: noisy top-2 + gates + expert lists (vectorized loads) --
        int t = bid * 256 + threadIdx.x;
        if (t >= TTOK) return;
        float4 L0 = *(const float4*)(logits + (size_t)t * NEXP);
        float4 L1 = *(const float4*)(logits + (size_t)t * NEXP + 4);
        float4 N0 = *(const float4*)(noise  + (size_t)t * NEXP);
        float4 N1 = *(const float4*)(noise  + (size_t)t * NEXP + 4);
        float l [8] = {L0.x, L0.y, L0.z, L0.w, L1.x, L1.y, L1.z, L1.w};
        float nz[8] = {N0.x, N0.y, N0.z, N0.w, N1.x, N1.y, N1.z, N1.w};

        float v0 = -1e30f, v1 = -1e30f;
        int i0 = 0, i1 = 0;
#pragma unroll
        for (int e = 0; e < NEXP; e++) {
            float sp = fmaxf(l[e], 0.f) + log1pf(expf(-fabsf(l[e])));
            float v  = l[e] + nz[e] * sp;
            if (v > v0)      { v1 = v0; i1 = i0; v0 = v; i0 = e; }
            else if (v > v1) { v1 = v;  i1 = e; }
        }
        float e1  = expf(v1 - v0);
        float den = 1.f + e1;
        float ga  = 1.f / den;
        float gb  = e1 / den;

        int s0 = atomicAdd(&g_count[i0], 1);
        g_tok[i0][s0] = t; g_aid[i0][s0] = 2 * t;     g_gate[i0][s0] = ga;
        int s1 = atomicAdd(&g_count[i1], 1);
        g_tok[i1][s1] = t; g_aid[i1][s1] = 2 * t + 1; g_gate[i1][s1] = gb;

    } else if (bid < PREP_RT + PREP_RX) {
        // ---- round_x: fp32 x -> fp16 (RNE), grid-stride --------------------
        int b = bid - PREP_RT;
        int i = b * 256 + threadIdx.x;
        const int stride = PREP_RX * 256;
        const int n4 = TTOK * DDIM / 4;
        for (; i < n4; i += stride) {
            float4 v = x[i];
            __half2 h0 = __floats2half2_rn(v.x, v.y);
            __half2 h1 = __floats2half2_rn(v.z, v.w);
            *(uint2*)(g_xh + (size_t)i * 4) =
                make_uint2(*(uint32_t*)&h0, *(uint32_t*)&h1);
        }

    } else {
        // ---- weight transpose + round: in[e][R][C] -> out[e][C][R] fp16 ----
        const float* in; __half* out; int R, C, bx, by, bz;
        if (bid < PREP_RT + PREP_RX + PREP_W1) {
            int b = bid - (PREP_RT + PREP_RX);
            in = W1; out = w1t; R = DDIM; C = HDIM;
            bx = b % (HDIM / 64);
            int r = b / (HDIM / 64);
            by = r % (DDIM / 64);
            bz = r / (DDIM / 64);
        } else {
            int b = bid - (PREP_RT + PREP_RX + PREP_W1);
            in = W2; out = w2t; R = HDIM; C = DDIM;
            bx = b % (DDIM / 64);
            int r = b / (DDIM / 64);
            by = r % (HDIM / 64);
            bz = r / (HDIM / 64);
        }
        size_t base = (size_t)bz * R * C;
        int c0 = bx * 64, r0 = by * 64;
        int tx = threadIdx.x & 15;          // float4 column
        int ty = threadIdx.x >> 4;          // row group
#pragma unroll
        for (int j = 0; j < 4; j++) {
            int row = ty + j * 16;
            float4 v = *(const float4*)(in + base + (size_t)(r0 + row) * C + c0 + tx * 4);
            ts[row][tx * 4 + 0] = v.x;
            ts[row][tx * 4 + 1] = v.y;
            ts[row][tx * 4 + 2] = v.z;
            ts[row][tx * 4 + 3] = v.w;
        }
        __syncthreads();
#pragma unroll
        for (int j = 0; j < 4; j++) {
            int oc = ty + j * 16;           // output row = original column
            __half2 h0 = __floats2half2_rn(ts[tx * 4 + 0][oc], ts[tx * 4 + 1][oc]);
            __half2 h1 = __floats2half2_rn(ts[tx * 4 + 2][oc], ts[tx * 4 + 3][oc]);
            *(uint2*)(out + base + (size_t)(c0 + oc) * R + r0 + tx * 4) =
                make_uint2(*(uint32_t*)&h0, *(uint32_t*)&h1);
        }
    }
}

// ---------------- flat M-tile list (compact grids, no empty-CTA waves) -------
__global__ void tilelist_kernel() {
    if (threadIdx.x != 0) return;
    int n = 0;
    for (int e = 0; e < NEXP; e++) {
        int cnt = g_count[e];
        for (int m0 = 0; m0 < cnt; m0 += 256) {
            g_tile_e [n] = e;
            g_tile_m0[n] = m0;
            n++;
        }
    }
    g_ntile = n;                       // <= 71 since sum(cnt) = 2*TTOK
}

// ============================================================================
// tcgen05 path — cg1 256x256 fp16; ALL 8 worker warps produce (2x in-flight
// cp.asyncs per SM), warps 0-3 run the epilogue afterwards.
// ============================================================================
#if HAS_TC

#define MBARRIER_INIT(addr, cnt) \
    asm volatile("mbarrier.init.shared.b64 [%0], %1;" :: "r"((uint32_t)(addr)), "r"((uint32_t)(cnt)) : "memory")

#define MBARRIER_WAIT_PARITY(mbar, par) do {                                            \
    uint32_t _m = (uint32_t)(mbar), _p = (uint32_t)(par), _d;                           \
    asm volatile("{\n\t.reg .pred p;\n\t"                                               \
        "mbarrier.try_wait.parity.acquire.cta.shared::cta.b64 p, [%1], %2;\n\t"         \
        "selp.b32 %0, 1, 0, p;\n\t}" : "=r"(_d) : "r"(_m), "r"(_p) : "memory");         \
    if (!_d) {                                                                          \
        asm volatile("{\n\t.reg .pred P1;\n\tWL_%=:\n\t"                                \
            "mbarrier.try_wait.parity.acquire.cta.shared::cta.b64 P1, [%0], %1, 0x989680;\n\t" \
            "@P1 bra.uni WD_%=;\n\tbra.uni WL_%=;\n\tWD_%=:\n\t}"                       \
            :: "r"(_m), "r"(_p) : "memory");                                            \
    }                                                                                   \
} while (0)

#define CPASYNC_ARRIVE_NOINC(mbar) \
    asm volatile("cp.async.mbarrier.arrive.noinc.shared::cta.b64 [%0];" :: "r"((uint32_t)(mbar)) : "memory")

#define TCGEN05_ALLOC(sa, n) \
    asm volatile("tcgen05.alloc.cta_group::1.sync.aligned.shared::cta.b32 [%0], %1;" \
                 :: "r"((uint32_t)(sa)), "r"((uint32_t)(n)) : "memory")
#define TCGEN05_DEALLOC(t, n) \
    asm volatile("tcgen05.dealloc.cta_group::1.sync.aligned.b32 %0, %1;" :: "r"(t), "r"((uint32_t)(n)))
#define TCGEN05_RELINQ() \
    asm volatile("tcgen05.relinquish_alloc_permit.cta_group::1.sync.aligned;")
#define TCGEN05_COMMIT(mbar) \
    asm volatile("tcgen05.commit.cta_group::1.mbarrier::arrive::one.shared::cluster.b64 [%0];" \
                 :: "r"((uint32_t)(mbar)) : "memory")
#define TCGEN05_FENCE_AFTER()  asm volatile("tcgen05.fence::after_thread_sync;" ::: "memory")
#define TCGEN05_FENCE_BEFORE() asm volatile("tcgen05.fence::before_thread_sync;" ::: "memory")
#define TCGEN05_WAIT_LD()      asm volatile("tcgen05.wait::ld.sync.aligned;" ::: "memory")
#define FENCE_PROXY_ASYNC()    asm volatile("fence.proxy.async.shared::cta;" ::: "memory")

#define TCGEN05_LD_32X32B_X32(r, ta) \
    asm volatile( \
        "tcgen05.ld.sync.aligned.32x32b.x32.b32 " \
        "{%0, %1, %2, %3, %4, %5, %6, %7, " \
        " %8, %9, %10, %11, %12, %13, %14, %15, " \
        " %16, %17, %18, %19, %20, %21, %22, %23, " \
        " %24, %25, %26, %27, %28, %29, %30, %31}, [%32];" \
        : "=r"((r)[0]),  "=r"((r)[1]),  "=r"((r)[2]),  "=r"((r)[3]), \
          "=r"((r)[4]),  "=r"((r)[5]),  "=r"((r)[6]),  "=r"((r)[7]), \
          "=r"((r)[8]),  "=r"((r)[9]),  "=r"((r)[10]), "=r"((r)[11]), \
          "=r"((r)[12]), "=r"((r)[13]), "=r"((r)[14]), "=r"((r)[15]), \
          "=r"((r)[16]), "=r"((r)[17]), "=r"((r)[18]), "=r"((r)[19]), \
          "=r"((r)[20]), "=r"((r)[21]), "=r"((r)[22]), "=r"((r)[23]), \
          "=r"((r)[24]), "=r"((r)[25]), "=r"((r)[26]), "=r"((r)[27]), \
          "=r"((r)[28]), "=r"((r)[29]), "=r"((r)[30]), "=r"((r)[31]) \
        : "r"(ta))

// K-major SW128 SMEM descriptor (LBO=1, SBO=64, version=1, layout SW128)
static constexpr uint64_t SMEM_DESC_BASE_SW128 =
    (uint64_t(2) << 61) | (uint64_t(1) << 46) | (uint64_t(64) << 32) | (uint64_t(1) << 16);
#define MAKE_SMEM_DESC(a) (SMEM_DESC_BASE_SW128 | ((uint64_t)((a) >> 4) & 0x3FFF))

__device__ __forceinline__ uint32_t elect_one_pred() {
    uint32_t p;
    asm volatile("{\n\t.reg .pred p;\n\telect.sync _|p, 0xFFFFFFFF;\n\tselp.b32 %0, 1, 0, p;\n\t}" : "=r"(p));
    return p;
}

// f16 SS MMA, cg1: D[128,256](f32) += A[128,16](f16) * B[256,16](f16)^T
__device__ __forceinline__ void mma_f16_ss(uint32_t d, uint64_t ad, uint64_t bd,
                                           uint32_t idesc, uint32_t en) {
    asm volatile(
        "{\n\t.reg .pred p;\n\tsetp.ne.u32 p, %4, 0;\n\t"
        "tcgen05.mma.cta_group::1.kind::f16 [%0], %1, %2, %3, {%5, %5, %5, %5}, p;\n\t}"
        :: "r"(d), "l"(ad), "l"(bd), "r"(idesc), "r"(en), "r"(0u) : "memory");
}
#endif  // HAS_TC

// CTA tile 256M x 256N, 3-stage cp.async pipeline, K-chunk = 64 halves (128B)
static constexpr int SMEM_TILE0   = 5120;
static constexpr int SMEM_STAGE   = 65536;            // A 32KB + B 32KB
static constexpr int SMEM_TOTAL_G = SMEM_TILE0 + 3 * SMEM_STAGE;  // 201728

// STAGE 1: h[aid] = fp16(relu(x[tok] @ W1^T + b1))     (K=1024, N=4096)
// STAGE 2: oscr[aid] = fp16((h[aid] @ W2^T + b2)*gate) (K=4096, N=1024)
template <int STAGE>
__global__ void __launch_bounds__(288, 1)
moe_gemm_tc(const float* __restrict__ bias) {
#if HAS_TC
    constexpr int KD  = (STAGE == 1) ? DDIM : HDIM;
    constexpr int ND  = (STAGE == 1) ? HDIM : DDIM;
    constexpr int NCH = KD / 64;                      // 64 halves per chunk
    // kind::f16: dtype F32 (bit4), atype/btype FP16 (=0), N=256, M=128
    constexpr uint32_t IDESC =
        (1u << 4) | ((256u / 8) << 17) | ((128u / 16) << 24);

    extern __shared__ char smem[];
    const uint32_t sb = smem_u32(smem);

    const int slot = blockIdx.y;
    if (slot >= g_ntile) return;                      // compact: few empties
    const int e   = g_tile_e [slot];
    const int m0  = g_tile_m0[slot];
    const int cnt = g_count[e];
    const int n0  = blockIdx.x * 256;

    int*   s_src  = (int*)  (smem + 64);
    int*   s_dst  = (int*)  (smem + 64 + 1024);
    float* s_gate = (float*)(smem + 64 + 2048);
    float* s_bias = (float*)(smem + 64 + 3072);

    const int tid = threadIdx.x, wid = tid >> 5, lid = tid & 31;

    for (int i = tid; i < 256; i += 288) {
        int cs = min(m0 + i, cnt - 1);
        s_src[i]  = (STAGE == 1) ? g_tok[e][cs] : g_aid[e][cs];
        s_dst[i]  = g_aid[e][cs];
        s_gate[i] = g_gate[e][cs];
        s_bias[i] = bias[e * ND + n0 + i];
    }
    if (tid == 0) {
        for (int s = 0; s < 3; s++) {
            MBARRIER_INIT(sb + 8  + s * 8, 256);  // full: 256 producer arrivals
            MBARRIER_INIT(sb + 32 + s * 8, 1);    // empty: 1 commit arrival
        }
        MBARRIER_INIT(sb + 56, 1);                // mma done
    }
    if (wid == 8) TCGEN05_ALLOC(sb, 512);
    __syncthreads();

    uint32_t tmem;
    asm volatile("ld.shared.b32 %0, [%1];" : "=r"(tmem) : "r"(sb));

    if (wid < 8) {
        // ---- ALL 8 worker warps produce: 2x outstanding cp.asyncs per SM ----
        // thread p in [0,256): c16 = 16B column, rb = row base (0..31);
        // rows rb + i*32 keep (row & 7) constant -> one swizzle term.
        const int p   = tid;
        const int c16 = p & 7;
        const int rb  = p >> 3;                   // 0..31
        const __half* Asrc = (STAGE == 1) ? g_xh : g_hscr;
        const __half* Bsrc = (STAGE == 1) ? (g_w1t + (size_t)e * HDIM * DDIM)
                                          : (g_w2t + (size_t)e * DDIM * HDIM);
        const uint32_t sw  = (uint32_t)((c16 * 16) ^ ((rb & 7) << 4));
        const uint32_t daB = (uint32_t)rb * 128 + sw;           // A dst base
        const uint32_t dbB = 32768 + (uint32_t)rb * 128 + sw;   // B dst base
        const __half* pa[8];
#pragma unroll
        for (int i = 0; i < 8; i++)
            pa[i] = Asrc + (size_t)s_src[rb + i * 32] * KD + c16 * 8;
        const __half* pbase = Bsrc + (size_t)(n0 + rb) * KD + c16 * 8;

        int st = 0, ph = 1;                       // producer phase starts at 1
        for (int c = 0; c < NCH; c++) {
            MBARRIER_WAIT_PARITY(sb + 32 + st * 8, ph);
            uint32_t base = sb + SMEM_TILE0 + st * SMEM_STAGE;
            int ko = c * 64;                      // 64 halves per chunk
#pragma unroll
            for (int i = 0; i < 8; i++)           // A: rows rb + i*32
                asm volatile("cp.async.cg.shared.global [%0], [%1], 16;"
                             :: "r"(base + daB + i * 4096), "l"(pa[i] + ko));
#pragma unroll
            for (int i = 0; i < 8; i++)           // B: rows rb + i*32 (const stride)
                asm volatile("cp.async.cg.shared.global [%0], [%1], 16;"
                             :: "r"(base + dbB + i * 4096),
                                "l"(pbase + (size_t)i * 32 * KD + ko));
            CPASYNC_ARRIVE_NOINC(sb + 8 + st * 8);
            if (++st == 3) { st = 0; ph ^= 1; }
        }

        // ---- consumers (warps 0-3): epilogue after MMA completes ----
        if (wid < 4) {
            MBARRIER_WAIT_PARITY(sb + 56, 0);
            TCGEN05_FENCE_AFTER();
#pragma unroll
            for (int mh = 0; mh < 2; mh++) {
                int  tr    = mh * 128 + wid * 32 + lid;
                bool valid = (m0 + tr) < cnt;
                int  drow  = s_dst[tr];
                float gt   = s_gate[tr];
                __half* hp = g_hscr + (size_t)drow * HDIM + n0;
                __half* fp = g_oscr + (size_t)drow * DDIM + n0;
                for (int cc = 0; cc < 8; cc++) {
                    uint32_t r[32];
                    TCGEN05_LD_32X32B_X32(r, tmem + mh * 256 + cc * 32);
                    TCGEN05_WAIT_LD();
                    if (valid) {
                        if (STAGE == 1) {
#pragma unroll
                            for (int q = 0; q < 32; q += 4) {
                                float t0 = fmaxf(__uint_as_float(r[q+0]) + s_bias[cc*32+q+0], 0.f);
                                float t1 = fmaxf(__uint_as_float(r[q+1]) + s_bias[cc*32+q+1], 0.f);
                                float t2 = fmaxf(__uint_as_float(r[q+2]) + s_bias[cc*32+q+2], 0.f);
                                float t3 = fmaxf(__uint_as_float(r[q+3]) + s_bias[cc*32+q+3], 0.f);
                                __half2 h0 = __floats2half2_rn(t0, t1);
                                __half2 h1 = __floats2half2_rn(t2, t3);
                                *(uint2*)(hp + cc * 32 + q) =
                                    make_uint2(*(uint32_t*)&h0, *(uint32_t*)&h1);
                            }
                        } else {
#pragma unroll
                            for (int q = 0; q < 32; q += 4) {
                                float t0 = (__uint_as_float(r[q+0]) + s_bias[cc*32+q+0]) * gt;
                                float t1 = (__uint_as_float(r[q+1]) + s_bias[cc*32+q+1]) * gt;
                                float t2 = (__uint_as_float(r[q+2]) + s_bias[cc*32+q+2]) * gt;
                                float t3 = (__uint_as_float(r[q+3]) + s_bias[cc*32+q+3]) * gt;
                                __half2 h0 = __floats2half2_rn(t0, t1);
                                __half2 h1 = __floats2half2_rn(t2, t3);
                                *(uint2*)(fp + cc * 32 + q) =
                                    make_uint2(*(uint32_t*)&h0, *(uint32_t*)&h1);
                            }
                        }
                    }
                }
            }
            TCGEN05_FENCE_BEFORE();
        }
    } else {
        // ---- MMA issuer: one elected thread ----
        if (elect_one_pred()) {
            int st = 0, ph = 0;
            for (int c = 0; c < NCH; c++) {
                MBARRIER_WAIT_PARITY(sb + 8 + st * 8, ph);
                FENCE_PROXY_ASYNC();
                uint32_t aaddr = sb + SMEM_TILE0 + st * SMEM_STAGE;
                uint64_t ad = MAKE_SMEM_DESC(aaddr);
                uint64_t bd = MAKE_SMEM_DESC(aaddr + 32768);
#pragma unroll
                for (int ka = 0; ka < 4; ka++) {  // 4 x K=16 per 128B chunk
                    uint32_t en = (c > 0 || ka > 0) ? 1u : 0u;
                    mma_f16_ss(tmem,       ad + ka * 2,        bd + ka * 2, IDESC, en);
                    mma_f16_ss(tmem + 256, ad + 1024 + ka * 2, bd + ka * 2, IDESC, en);
                }
                TCGEN05_COMMIT(sb + 32 + st * 8);
                if (++st == 3) { st = 0; ph ^= 1; }
            }
            TCGEN05_COMMIT(sb + 56);
        }
    }

    __syncthreads();
    if (wid == 8) {
        TCGEN05_RELINQ();
        TCGEN05_DEALLOC(tmem, 512);
    }
#else
    (void)bias;   // plain-sm_103 build: empty kernel; fallback does the work
#endif
}

// ============================================================================
// Fallback path: warp-level mma.sync m16n8k16 fp16 (compiles on plain sm_103)
// ============================================================================
template <int STAGE>
__global__ void __launch_bounds__(256)
moe_gemm_fb(const float* __restrict__ bias) {
    if (g_use_tc) return;

    constexpr int KD = (STAGE == 1) ? DDIM : HDIM;
    constexpr int ND = (STAGE == 1) ? HDIM : DDIM;
    constexpr int KT = KD / 16;

    const int e   = blockIdx.z;
    const int cnt = g_count[e];
    const int m0  = blockIdx.y * 128;
    if (m0 >= cnt) return;
    const int n0  = blockIdx.x * 128;

    const __half* X  = (STAGE == 1) ? g_xh : g_hscr;
    const __half* Bw = (STAGE == 1) ? (g_w1t + (size_t)e * HDIM * DDIM)
                                    : (g_w2t + (size_t)e * DDIM * HDIM);

    __shared__ unsigned As[2][128 * 9];
    __shared__ unsigned Bs[2][128 * 9];
    __shared__ int   s_src[128];
    __shared__ int   s_dst[128];
    __shared__ float s_gate[128];
    __shared__ float s_bias[128];

    const int tid = threadIdx.x;
    for (int i = tid; i < 128; i += 256) {
        int cs = min(m0 + i, cnt - 1);
        s_src[i]  = (STAGE == 1) ? g_tok[e][cs] : g_aid[e][cs];
        s_dst[i]  = g_aid[e][cs];
        s_gate[i] = g_gate[e][cs];
        s_bias[i] = bias[e * ND + n0 + i];
    }
    __syncthreads();

    auto fill = [&](int buf, int kt) {
        int row = tid >> 1, h16 = tid & 1;
        cp16(&As[buf][row * 9 + h16 * 4],
             X + (size_t)s_src[row] * KD + kt * 16 + h16 * 8);
        cp16(&Bs[buf][row * 9 + h16 * 4],
             Bw + (size_t)(n0 + row) * KD + kt * 16 + h16 * 8);
        cp_commit();
    };

    fill(0, 0);

    const int lane = tid & 31;
    const int wid  = tid >> 5;
    const int am   = (wid & 3) * 32;
    const int bn   = (wid >> 2) * 64;
    const int g    = lane >> 2;
    const int t    = lane & 3;

    float acc[2][8][4];
#pragma unroll
    for (int mt = 0; mt < 2; mt++)
#pragma unroll
        for (int nt = 0; nt < 8; nt++)
#pragma unroll
            for (int q = 0; q < 4; q++) acc[mt][nt][q] = 0.f;

    int buf = 0;
    for (int kt = 0; kt < KT; ++kt) {
        if (kt + 1 < KT) { fill(buf ^ 1, kt + 1); cp_wait1(); }
        else             { cp_wait0(); }
        __syncthreads();

        unsigned a[2][4], b[8][2];
#pragma unroll
        for (int mt = 0; mt < 2; mt++) {
            int r0 = am + mt * 16 + g;
            a[mt][0] = As[buf][r0 * 9 + t];
            a[mt][1] = As[buf][(r0 + 8) * 9 + t];
            a[mt][2] = As[buf][r0 * 9 + t + 4];
            a[mt][3] = As[buf][(r0 + 8) * 9 + t + 4];
        }
#pragma unroll
        for (int nt = 0; nt < 8; nt++) {
            int rn = bn + nt * 8 + g;
            b[nt][0] = Bs[buf][rn * 9 + t];
            b[nt][1] = Bs[buf][rn * 9 + t + 4];
        }
#pragma unroll
        for (int mt = 0; mt < 2; mt++)
#pragma unroll
            for (int nt = 0; nt < 8; nt++)
                mma16(acc[mt][nt], a[mt], b[nt]);

        __syncthreads();
        buf ^= 1;
    }

#pragma unroll
    for (int mt = 0; mt < 2; mt++) {
#pragma unroll
        for (int nt = 0; nt < 8; nt++) {
            int col = bn + nt * 8 + 2 * t;
#pragma unroll
            for (int half = 0; half < 2; half++) {
                int lrow = am + mt * 16 + g + half * 8;
                if (m0 + lrow < cnt) {
                    float v0 = acc[mt][nt][half * 2 + 0] + s_bias[col];
                    float v1 = acc[mt][nt][half * 2 + 1] + s_bias[col + 1];
                    if (STAGE == 1) {
                        __half2 hv = __floats2half2_rn(fmaxf(v0, 0.f), fmaxf(v1, 0.f));
                        *(uint32_t*)(g_hscr + (size_t)s_dst[lrow] * HDIM + n0 + col) =
                            *(uint32_t*)&hv;
                    } else {
                        float gg = s_gate[lrow];
                        __half2 hv = __floats2half2_rn(v0 * gg, v1 * gg);
                        *(uint32_t*)(g_oscr + (size_t)s_dst[lrow] * DDIM + n0 + col) =
                            *(uint32_t*)&hv;
                    }
                }
            }
        }
    }
}

// ---------------- combine the two per-token slots (fp16 -> fp32) -------------
__global__ void combine_kernel(float4* __restrict__ out) {
    int i = blockIdx.x * blockDim.x + threadIdx.x;
    int stride = gridDim.x * blockDim.x;
    const int n4 = TTOK * DDIM / 4;
    for (; i < n4; i += stride) {
        int t = i >> 8;            // DDIM/4 = 256
        int c = i & 255;
        uint2 ua = *(const uint2*)(g_oscr + (size_t)(2 * t) * DDIM + c * 4);
        uint2 ub = *(const uint2*)(g_oscr + (size_t)(2 * t + 1) * DDIM + c * 4);
        float2 a0 = __half22float2(*(__half2*)&ua.x);
        float2 a1 = __half22float2(*(__half2*)&ua.y);
        float2 b0 = __half22float2(*(__half2*)&ub.x);
        float2 b1 = __half22float2(*(__half2*)&ub.y);
        out[i] = make_float4(a0.x + b0.x, a0.y + b0.y, a1.x + b1.x, a1.y + b1.y);
    }
}

// ---------------- launcher ---------------------------------------------------
extern "C" void kernel_launch(void* const* d_in, const int* in_sizes, int n_in,
                              void* d_out, int out_size) {
    const float* x      = (const float*)d_in[0];   // [4,2048,1024]
    const float* logits = (const float*)d_in[1];   // [4,2048,8]
    const float* noise  = (const float*)d_in[2];   // [4,2048,8]
    const float* W1     = (const float*)d_in[3];   // [8,1024,4096]
    const float* b1     = (const float*)d_in[4];   // [8,4096]
    const float* W2     = (const float*)d_in[5];   // [8,4096,1024]
    const float* b2     = (const float*)d_in[6];   // [8,1024]
    float* out          = (float*)d_out;           // [4,2048,1024]
    (void)in_sizes; (void)n_in; (void)out_size;

    static __half* w1t_p = nullptr;
    static __half* w2t_p = nullptr;
    if (!w1t_p) { cudaGetSymbolAddress((void**)&w1t_p, g_w1t);
                  cudaGetSymbolAddress((void**)&w2t_p, g_w2t); }

    cudaFuncSetAttribute(moe_gemm_tc<1>, cudaFuncAttributeMaxDynamicSharedMemorySize, SMEM_TOTAL_G);
    cudaFuncSetAttribute(moe_gemm_tc<2>, cudaFuncAttributeMaxDynamicSharedMemorySize, SMEM_TOTAL_G);

    init_kernel<<<1, 32>>>();
    // fused prep: router + round_x + transpose(W1) + transpose(W2) in ONE launch
    prep_kernel<<<PREP_TOTAL, 256>>>((const float4*)x, logits, noise,
                                     W1, W2, w1t_p, w2t_p);
    tilelist_kernel<<<1, 32>>>();

    // GEMM1: compact flat-tile grid (<= ~71 active slots x 16 N-tiles)
    moe_gemm_tc<1><<<dim3(HDIM / 256, MAXTILE, 1), 288, SMEM_TOTAL_G>>>(b1);
    moe_gemm_fb<1><<<dim3(HDIM / 128, TTOK / 128, NEXP), 256>>>(b1);
    // GEMM2: compact flat-tile grid (<= ~71 active slots x 4 N-tiles)
    moe_gemm_tc<2><<<dim3(DDIM / 256, MAXTILE, 1), 288, SMEM_TOTAL_G>>>(b2);
    moe_gemm_fb<2><<<dim3(DDIM / 128, TTOK / 128, NEXP), 256>>>(b2);

    combine_kernel<<<1024, 256>>>((float4*)out);
}